// round 13
// baseline (speedup 1.0000x reference)
#include <cuda_runtime.h>
#include <math.h>
#include <stdint.h>

#define FULL 0xffffffffu
#define T_STEPS 32
#define BATCH   128
#define NQ      8

// Closed-form QLSTM (derived R2, verified):
//   <Z_w> = prod_{k=0..w} cos(theta_k)*cos(q_k)  (w>=1);  <Z_0> = prod_{k=1..7} ...
// q = W [x;h] + b (first 8 rows), identical for all 4 circuits.
// Per step: Q_j = masked prod of cos(q_k); gate_c = nonlin(Cpref_c[j] * Q_j).
// R13: R9 frozen base + ONE surgical change: step 0 peeled and executed
// before the first named barrier (h(-1)=0 -> th0=qx0, computed inline by
// warp 0), hiding the producer-warp-1 startup latency.

__device__ __forceinline__ float tanh_ap(float x) {
    float y;
    asm("tanh.approx.f32 %0, %1;" : "=f"(y) : "f"(x));
    return y;
}

__device__ __forceinline__ void bar_arrive(int id, int cnt) {
    asm volatile("bar.arrive %0, %1;" :: "r"(id), "r"(cnt));
}
__device__ __forceinline__ void bar_sync_named(int id, int cnt) {
    asm volatile("bar.sync %0, %1;" :: "r"(id), "r"(cnt) : "memory");
}

// Block = 160 threads. Warp 0: recurrence (lane&7 = unit j; all 4 gates local).
// Warps 1-4: producers; warp w computes qx[t][:] for t in [(w-1)*8, w*8).
__global__ void __launch_bounds__(160, 1) qlstm_kernel(
    const float* __restrict__ x,   // [32,128,64]
    const float* __restrict__ W,   // [16,72]
    const float* __restrict__ bv,  // [16]
    const float* __restrict__ fp, const float* __restrict__ ip,
    const float* __restrict__ up, const float* __restrict__ op,
    float* __restrict__ out) {

    __shared__ float s_qx[T_STEPS * NQ];
    __shared__ __align__(16) float s_h[8];
    __shared__ __align__(16) float s_cq[8];

    int tid  = threadIdx.x;
    int lane = tid & 31;
    int wid  = tid >> 5;
    int b    = blockIdx.x;
    int j    = lane & 7;
    int gb   = lane & 24;

    if (wid >= 1) {
        // ---- producer warp: qx[t][j] = b_j + W_x[j,:] . x[t,b,:] ----
        int cc = lane >> 3;   // k-slice
        const float4* wxp = (const float4*)(W + j * 72 + 16 * cc);
        float4 w0 = wxp[0], w1 = wxp[1], w2 = wxp[2], w3 = wxp[3];
        float bj = bv[j];
        int t0 = (wid - 1) * 8;
        #pragma unroll
        for (int tt = 0; tt < 8; ++tt) {
            int t = t0 + tt;
            const float4* xp = (const float4*)(x + (t * BATCH + b) * 64 + 16 * cc);
            float4 v0 = xp[0], v1 = xp[1], v2 = xp[2], v3 = xp[3];
            float p0 = w0.x * v0.x + w0.y * v0.y + w0.z * v0.z + w0.w * v0.w;
            float p1 = w1.x * v1.x + w1.y * v1.y + w1.z * v1.z + w1.w * v1.w;
            float p2 = w2.x * v2.x + w2.y * v2.y + w2.z * v2.z + w2.w * v2.w;
            float p3 = w3.x * v3.x + w3.y * v3.y + w3.z * v3.z + w3.w * v3.w;
            float part = (p0 + p1) + (p2 + p3);
            part += __shfl_xor_sync(FULL, part, 8);
            part += __shfl_xor_sync(FULL, part, 16);
            if (cc == 0) s_qx[t * NQ + j] = part + bj;
        }
        __threadfence_block();
        bar_arrive(wid, 64);
        return;
    }

    // ---- recurrence warp setup (overlaps producers) ----
    // inline qx for t=0: issue loads first so latency overlaps the setup below
    int cc0 = lane >> 3;
    const float4* xp0 = (const float4*)(x + b * 64 + 16 * cc0);
    float4 e0 = xp0[0], e1 = xp0[1], e2 = xp0[2], e3 = xp0[3];
    const float4* wx0p = (const float4*)(W + j * 72 + 16 * cc0);
    float4 u0 = wx0p[0], u1 = wx0p[1], u2 = wx0p[2], u3 = wx0p[3];
    float bj0 = bv[j];

    const float4* whp = (const float4*)(W + j * 72 + 64);
    float4 wa = whp[0], wb4 = whp[1];

    bool j0 = (j == 0);
    bool m0 = !j0;
    bool m2 = j0 || (2 <= j), m3 = j0 || (3 <= j), m4 = j0 || (4 <= j);
    bool m5 = j0 || (5 <= j), m6 = j0 || (6 <= j), m7 = j0 || (j == 7);

    // one-time Cpref via shfl fan (prologue; overlapped with producers)
    #define MASKED_TREE(res, val)                                        \
        {                                                                \
            float q0 = __shfl_sync(FULL, (val), gb | 0);                 \
            float q1 = __shfl_sync(FULL, (val), gb | 1);                 \
            float q2 = __shfl_sync(FULL, (val), gb | 2);                 \
            float q3 = __shfl_sync(FULL, (val), gb | 3);                 \
            float q4 = __shfl_sync(FULL, (val), gb | 4);                 \
            float q5 = __shfl_sync(FULL, (val), gb | 5);                 \
            float q6 = __shfl_sync(FULL, (val), gb | 6);                 \
            float q7 = __shfl_sync(FULL, (val), gb | 7);                 \
            float a0 = m0 ? q0 : 1.f;                                    \
            float a2 = m2 ? q2 : 1.f;                                    \
            float a3 = m3 ? q3 : 1.f;                                    \
            float a4 = m4 ? q4 : 1.f;                                    \
            float a5 = m5 ? q5 : 1.f;                                    \
            float a6 = m6 ? q6 : 1.f;                                    \
            float a7 = m7 ? q7 : 1.f;                                    \
            res = ((a0 * q1) * (a2 * a3)) * ((a4 * a5) * (a6 * a7));     \
        }

    float cf = __cosf(fp[j]);
    float ci = __cosf(ip[j]);
    float cu = __cosf(up[j]);
    float co = __cosf(op[j]);
    float Cf, Ci, Cu, Co;
    MASKED_TREE(Cf, cf); Cf *= 0.5f;
    MASKED_TREE(Ci, ci); Ci *= 0.5f;
    MASKED_TREE(Cu, cu);
    MASKED_TREE(Co, co); Co *= 0.5f;
    #undef MASKED_TREE

    bool store8 = (lane < 8);
    float h = 0.f, cstate = 0.f;

    // ---- peeled step 0 (before any barrier; no s_qx, no h-exchange) ----
    {
        float p0 = u0.x * e0.x + u0.y * e0.y + u0.z * e0.z + u0.w * e0.w;
        float p1 = u1.x * e1.x + u1.y * e1.y + u1.z * e1.z + u1.w * e1.w;
        float p2 = u2.x * e2.x + u2.y * e2.y + u2.z * e2.z + u2.w * e2.w;
        float p3 = u3.x * e3.x + u3.y * e3.y + u3.z * e3.z + u3.w * e3.w;
        float part = (p0 + p1) + (p2 + p3);
        part += __shfl_xor_sync(FULL, part, 8);
        part += __shfl_xor_sync(FULL, part, 16);
        float qx0 = part + bj0;

        float cq = __cosf(qx0);
        if (store8) s_cq[j] = cq;
        __syncwarp();
        float4 qA = *(const float4*)&s_cq[0];
        float4 qB = *(const float4*)&s_cq[4];
        float a0 = m0 ? qA.x : 1.f;
        float a2 = m2 ? qA.z : 1.f;
        float a3 = m3 ? qA.w : 1.f;
        float a4 = m4 ? qB.x : 1.f;
        float a5 = m5 ? qB.y : 1.f;
        float a6 = m6 ? qB.z : 1.f;
        float a7 = m7 ? qB.w : 1.f;
        float Q = ((a0 * qA.y) * (a2 * a3)) * ((a4 * a5) * (a6 * a7));

        float g = tanh_ap(Cu * Q);
        float i = fmaf(0.5f, tanh_ap(Ci * Q), 0.5f);
        float o = fmaf(0.5f, tanh_ap(Co * Q), 0.5f);
        cstate = i * g;                       // f * 0 dropped
        h = o * tanh_ap(cstate);

        if (store8) s_h[j] = h;
        __syncwarp();
        if (store8) out[b * NQ + j] = h;
    }

    // ---- steady-state loop: R9 body verbatim ----
    #pragma unroll 1
    for (int seg = 0; seg < 4; ++seg) {
        bar_sync_named(seg + 1, 64);   // producer warp seg+1 landed its qx range
        int tbeg = (seg == 0) ? 1 : 0; // seg 0: t=0 already done

        #pragma unroll 8
        for (int tt = tbeg; tt < 8; ++tt) {
            int t = seg * 8 + tt;
            float qx = s_qx[t * NQ + j];   // off-chain LDS

            // ---- exchange h via SMEM ----
            float4 hA = *(const float4*)&s_h[0];
            float4 hB = *(const float4*)&s_h[4];
            float s01 = wa.x  * hA.x + wa.y  * hA.y;
            float s23 = wa.z  * hA.z + wa.w  * hA.w;
            float s45 = wb4.x * hB.x + wb4.y * hB.y;
            float s67 = wb4.z * hB.z + wb4.w * hB.w;
            float th  = (qx + (s01 + s23)) + (s45 + s67);
            float cq  = __cosf(th);

            // ---- exchange cq via SMEM ----
            if (store8) s_cq[j] = cq;
            __syncwarp();
            float4 qA = *(const float4*)&s_cq[0];
            float4 qB = *(const float4*)&s_cq[4];

            float a0 = m0 ? qA.x : 1.f;
            float a2 = m2 ? qA.z : 1.f;
            float a3 = m3 ? qA.w : 1.f;
            float a4 = m4 ? qB.x : 1.f;
            float a5 = m5 ? qB.y : 1.f;
            float a6 = m6 ? qB.z : 1.f;
            float a7 = m7 ? qB.w : 1.f;
            float Q = ((a0 * qA.y) * (a2 * a3)) * ((a4 * a5) * (a6 * a7));

            // ---- all 4 gates local ----
            float g = tanh_ap(Cu * Q);
            float i = fmaf(0.5f, tanh_ap(Ci * Q), 0.5f);
            float f = fmaf(0.5f, tanh_ap(Cf * Q), 0.5f);
            float o = fmaf(0.5f, tanh_ap(Co * Q), 0.5f);

            cstate = fmaf(f, cstate, i * g);
            h = o * tanh_ap(cstate);

            // publish h(t) for next step (syncwarp doubles as release fence)
            if (store8) s_h[j] = h;
            __syncwarp();

            if (store8) out[(t * BATCH + b) * NQ + j] = h;
        }
    }

    if (store8) {
        out[T_STEPS * BATCH * NQ + b * NQ + j]              = h;       // hx
        out[T_STEPS * BATCH * NQ + BATCH * NQ + b * NQ + j] = cstate;  // cx
    }
}

extern "C" void kernel_launch(void* const* d_in, const int* in_sizes, int n_in,
                              void* d_out, int out_size) {
    const float* x  = (const float*)d_in[0];
    const float* W  = (const float*)d_in[1];
    const float* bv = (const float*)d_in[2];
    const float* fp = (const float*)d_in[3];
    const float* ip = (const float*)d_in[4];
    const float* up = (const float*)d_in[5];
    const float* op = (const float*)d_in[6];
    float* out = (float*)d_out;

    qlstm_kernel<<<BATCH, 160>>>(x, W, bv, fp, ip, up, op, out);
}

// round 14
// speedup vs baseline: 1.1644x; 1.1644x over previous
#include <cuda_runtime.h>
#include <math.h>
#include <stdint.h>

#define FULL 0xffffffffu
#define T_STEPS 32
#define BATCH   128
#define NQ      8

// Closed-form QLSTM (derived R2, verified):
//   <Z_w> = prod_{k=0..w} cos(theta_k)*cos(q_k)  (w>=1);  <Z_0> = prod_{k=1..7} ...
// q = W [x;h] + b (first 8 rows), identical for all 4 circuits.
// Per step: Q_j = masked prod of cos(q_k); gate_c = nonlin(Cpref_c[j] * Q_j).
// R14: R9 frozen structure. ONLY change: f/i/o sigmoid-gate tanh computed as
// FMA-pipe degree-7 odd polynomial (valid: |C*Q| <= 0.5), cutting per-step
// MUFU-issue serialization from 6 ops to 3 (cos, tanh_g, tanh_c).

__device__ __forceinline__ float tanh_ap(float x) {
    float y;
    asm("tanh.approx.f32 %0, %1;" : "=f"(y) : "f"(x));
    return y;
}

// odd deg-7 Taylor of tanh, |x| <= 0.5, max err ~4.3e-5 (FMA pipe, no MUFU)
__device__ __forceinline__ float tanh_poly_half(float x) {
    float t = x * x;
    float p = fmaf(-0.05396825f, t, 0.13333333f);   // -17/315, 2/15
    p = fmaf(p, t, -0.33333333f);                   // -1/3
    p = fmaf(p, t, 1.0f);
    return x * p;
}

__device__ __forceinline__ void bar_arrive(int id, int cnt) {
    asm volatile("bar.arrive %0, %1;" :: "r"(id), "r"(cnt));
}
__device__ __forceinline__ void bar_sync_named(int id, int cnt) {
    asm volatile("bar.sync %0, %1;" :: "r"(id), "r"(cnt) : "memory");
}

// Block = 160 threads. Warp 0: recurrence (lane&7 = unit j; all 4 gates local).
// Warps 1-4: producers; warp w computes qx[t][:] for t in [(w-1)*8, w*8).
__global__ void __launch_bounds__(160, 1) qlstm_kernel(
    const float* __restrict__ x,   // [32,128,64]
    const float* __restrict__ W,   // [16,72]
    const float* __restrict__ bv,  // [16]
    const float* __restrict__ fp, const float* __restrict__ ip,
    const float* __restrict__ up, const float* __restrict__ op,
    float* __restrict__ out) {

    __shared__ float s_qx[T_STEPS * NQ];
    __shared__ __align__(16) float s_h[8];
    __shared__ __align__(16) float s_cq[8];

    int tid  = threadIdx.x;
    int lane = tid & 31;
    int wid  = tid >> 5;
    int b    = blockIdx.x;
    int j    = lane & 7;
    int gb   = lane & 24;

    if (wid >= 1) {
        // ---- producer warp: qx[t][j] = b_j + W_x[j,:] . x[t,b,:] ----
        int cc = lane >> 3;   // k-slice
        const float4* wxp = (const float4*)(W + j * 72 + 16 * cc);
        float4 w0 = wxp[0], w1 = wxp[1], w2 = wxp[2], w3 = wxp[3];
        float bj = bv[j];
        int t0 = (wid - 1) * 8;
        #pragma unroll
        for (int tt = 0; tt < 8; ++tt) {
            int t = t0 + tt;
            const float4* xp = (const float4*)(x + (t * BATCH + b) * 64 + 16 * cc);
            float4 v0 = xp[0], v1 = xp[1], v2 = xp[2], v3 = xp[3];
            float p0 = w0.x * v0.x + w0.y * v0.y + w0.z * v0.z + w0.w * v0.w;
            float p1 = w1.x * v1.x + w1.y * v1.y + w1.z * v1.z + w1.w * v1.w;
            float p2 = w2.x * v2.x + w2.y * v2.y + w2.z * v2.z + w2.w * v2.w;
            float p3 = w3.x * v3.x + w3.y * v3.y + w3.z * v3.z + w3.w * v3.w;
            float part = (p0 + p1) + (p2 + p3);
            part += __shfl_xor_sync(FULL, part, 8);
            part += __shfl_xor_sync(FULL, part, 16);
            if (cc == 0) s_qx[t * NQ + j] = part + bj;
        }
        __threadfence_block();
        bar_arrive(wid, 64);
        return;
    }

    // ---- recurrence warp setup (overlaps producers) ----
    const float4* whp = (const float4*)(W + j * 72 + 64);
    float4 wa = whp[0], wb4 = whp[1];

    bool j0 = (j == 0);
    bool m0 = !j0;
    bool m2 = j0 || (2 <= j), m3 = j0 || (3 <= j), m4 = j0 || (4 <= j);
    bool m5 = j0 || (5 <= j), m6 = j0 || (6 <= j), m7 = j0 || (j == 7);

    // one-time Cpref via shfl fan (prologue; overlapped with producers)
    #define MASKED_TREE(res, val)                                        \
        {                                                                \
            float q0 = __shfl_sync(FULL, (val), gb | 0);                 \
            float q1 = __shfl_sync(FULL, (val), gb | 1);                 \
            float q2 = __shfl_sync(FULL, (val), gb | 2);                 \
            float q3 = __shfl_sync(FULL, (val), gb | 3);                 \
            float q4 = __shfl_sync(FULL, (val), gb | 4);                 \
            float q5 = __shfl_sync(FULL, (val), gb | 5);                 \
            float q6 = __shfl_sync(FULL, (val), gb | 6);                 \
            float q7 = __shfl_sync(FULL, (val), gb | 7);                 \
            float a0 = m0 ? q0 : 1.f;                                    \
            float a2 = m2 ? q2 : 1.f;                                    \
            float a3 = m3 ? q3 : 1.f;                                    \
            float a4 = m4 ? q4 : 1.f;                                    \
            float a5 = m5 ? q5 : 1.f;                                    \
            float a6 = m6 ? q6 : 1.f;                                    \
            float a7 = m7 ? q7 : 1.f;                                    \
            res = ((a0 * q1) * (a2 * a3)) * ((a4 * a5) * (a6 * a7));     \
        }

    float cf = __cosf(fp[j]);
    float ci = __cosf(ip[j]);
    float cu = __cosf(up[j]);
    float co = __cosf(op[j]);
    float Cf, Ci, Cu, Co;
    MASKED_TREE(Cf, cf); Cf *= 0.5f;
    MASKED_TREE(Ci, ci); Ci *= 0.5f;
    MASKED_TREE(Cu, cu);
    MASKED_TREE(Co, co); Co *= 0.5f;
    #undef MASKED_TREE

    bool store8 = (lane < 8);
    if (store8) s_h[j] = 0.f;       // h(t=-1) = 0
    __syncwarp();

    float h = 0.f, cstate = 0.f;

    #pragma unroll 1
    for (int seg = 0; seg < 4; ++seg) {
        bar_sync_named(seg + 1, 64);   // producer warp seg+1 landed its qx range

        #pragma unroll
        for (int tt = 0; tt < 8; ++tt) {
            int t = seg * 8 + tt;
            float qx = s_qx[t * NQ + j];   // off-chain LDS

            // ---- exchange h via SMEM (s_h already holds h(t-1)) ----
            float4 hA = *(const float4*)&s_h[0];
            float4 hB = *(const float4*)&s_h[4];
            float s01 = wa.x  * hA.x + wa.y  * hA.y;
            float s23 = wa.z  * hA.z + wa.w  * hA.w;
            float s45 = wb4.x * hB.x + wb4.y * hB.y;
            float s67 = wb4.z * hB.z + wb4.w * hB.w;
            float th  = (qx + (s01 + s23)) + (s45 + s67);
            float cq  = __cosf(th);

            // ---- exchange cq via SMEM ----
            if (store8) s_cq[j] = cq;
            __syncwarp();
            float4 qA = *(const float4*)&s_cq[0];
            float4 qB = *(const float4*)&s_cq[4];

            float a0 = m0 ? qA.x : 1.f;
            float a2 = m2 ? qA.z : 1.f;
            float a3 = m3 ? qA.w : 1.f;
            float a4 = m4 ? qB.x : 1.f;
            float a5 = m5 ? qB.y : 1.f;
            float a6 = m6 ? qB.z : 1.f;
            float a7 = m7 ? qB.w : 1.f;
            float Q = ((a0 * qA.y) * (a2 * a3)) * ((a4 * a5) * (a6 * a7));

            // ---- gates: g via MUFU; f/i/o via FMA-pipe poly (|arg| <= 0.5) ----
            float g = tanh_ap(Cu * Q);
            float i = fmaf(0.5f, tanh_poly_half(Ci * Q), 0.5f);
            float f = fmaf(0.5f, tanh_poly_half(Cf * Q), 0.5f);
            float o = fmaf(0.5f, tanh_poly_half(Co * Q), 0.5f);

            cstate = fmaf(f, cstate, i * g);
            h = o * tanh_ap(cstate);

            // publish h(t) for next step (syncwarp doubles as release fence)
            if (store8) s_h[j] = h;
            __syncwarp();

            if (store8) out[(t * BATCH + b) * NQ + j] = h;
        }
    }

    if (store8) {
        out[T_STEPS * BATCH * NQ + b * NQ + j]              = h;       // hx
        out[T_STEPS * BATCH * NQ + BATCH * NQ + b * NQ + j] = cstate;  // cx
    }
}

extern "C" void kernel_launch(void* const* d_in, const int* in_sizes, int n_in,
                              void* d_out, int out_size) {
    const float* x  = (const float*)d_in[0];
    const float* W  = (const float*)d_in[1];
    const float* bv = (const float*)d_in[2];
    const float* fp = (const float*)d_in[3];
    const float* ip = (const float*)d_in[4];
    const float* up = (const float*)d_in[5];
    const float* op = (const float*)d_in[6];
    float* out = (float*)d_out;

    qlstm_kernel<<<BATCH, 160>>>(x, W, bv, fp, ip, up, op, out);
}